// round 7
// baseline (speedup 1.0000x reference)
#include <cuda_runtime.h>
#include <cuda_fp16.h>
#include <cstdint>

#define VOCAB 14
#define EMBED 10
#define HID   50
#define HP    64          // padded unit slots (cached-k + gate-init tables)
#define KC    8           // k's cached in registers as fp32 (exact)
#define KS    (HID - KC)  // streamed k's (fp16)
#define SROW  52          // sH row stride in float2
#define TLEN  2048
#define NBATCH 4096
#define ROWS  4           // batch rows per warp

typedef unsigned long long ull;

// gWk[k][u] (fp32, padded): (0.5*Wi, 0.5*Wf, Wg, 0.5*Wo) — k<KC reg-cached
// gWH[(k-KC)*32 + lane]   : uint4 of 8 halves {i,f,g,o}(u1=lane), {i,f,g,o}(u2=lane+32)
// gXT[v][u] (fp32)        : per-token gate init, same scaling
__device__ float4 gWk[HID * HP];
__device__ __align__(16) __half gWH[KS * 32 * 8];
__device__ float4 gXT[VOCAB * HP];
__device__ float  gq[HID];
__device__ float  gc0;

// ---------------------------------------------------------------------------
__global__ void prep_kernel(const float* __restrict__ emb,
                            const float* __restrict__ W_ih,
                            const float* __restrict__ W_hh,
                            const float* __restrict__ b_ih,
                            const float* __restrict__ b_hh,
                            const float* __restrict__ W1,
                            const float* __restrict__ b1,
                            const float* __restrict__ W2,
                            const float* __restrict__ b2)
{
    int tid = threadIdx.x;

    for (int i = tid; i < HID * HP; i += blockDim.x) {
        int k = i / HP, u = i % HP;
        float4 w = make_float4(0.f, 0.f, 0.f, 0.f);
        if (u < HID) {
            w.x = 0.5f * W_hh[(0 * HID + u) * HID + k];
            w.y = 0.5f * W_hh[(1 * HID + u) * HID + k];
            w.z =        W_hh[(2 * HID + u) * HID + k];
            w.w = 0.5f * W_hh[(3 * HID + u) * HID + k];
        }
        gWk[i] = w;
    }

    // fp16 streamed table: per (k, lane) 8 halves = u1{i,f,g,o}, u2{i,f,g,o}
    for (int i = tid; i < KS * 32; i += blockDim.x) {
        int k = KC + i / 32, L = i % 32;
        __half* p = gWH + i * 8;
        int u1 = L, u2 = L + 32;
        #pragma unroll
        for (int g = 0; g < 4; g++) {
            float s = (g == 2) ? 1.0f : 0.5f;
            p[g] = __float2half_rn(s * W_hh[(g * HID + u1) * HID + k]);
            p[4 + g] = (u2 < HID)
                ? __float2half_rn(s * W_hh[(g * HID + u2) * HID + k])
                : __float2half_rn(0.0f);
        }
    }

    for (int i = tid; i < VOCAB * HP; i += blockDim.x) {
        int v = i / HP, u = i % HP;
        float4 x = make_float4(0.f, 0.f, 0.f, 0.f);
        if (u < HID) {
            float* px = reinterpret_cast<float*>(&x);
            #pragma unroll
            for (int g = 0; g < 4; g++) {
                int c = g * HID + u;
                float s = b_ih[c] + b_hh[c];
                #pragma unroll
                for (int e = 0; e < EMBED; e++)
                    s += emb[v * EMBED + e] * W_ih[c * EMBED + e];
                px[g] = (g == 2) ? s : 0.5f * s;
            }
        }
        gXT[i] = x;
    }

    for (int u = tid; u < HID; u += blockDim.x) {
        float s = 0.f;
        for (int m = 0; m < HID; m++) s += W2[m] * W1[m * HID + u];
        gq[u] = s;
    }
    if (tid == 0) {
        float s = b2[0];
        for (int m = 0; m < HID; m++) s += W2[m] * b1[m];
        gc0 = s;
    }
}

// ---------------------------------------------------------------------------
__device__ __forceinline__ ull ffma2(ull a, ull b, ull c) {
    ull d;
    asm("fma.rn.f32x2 %0, %1, %2, %3;" : "=l"(d) : "l"(a), "l"(b), "l"(c));
    return d;
}
__device__ __forceinline__ ull pk2(float x, float y) {
    ull d;
    asm("mov.b64 %0, {%1, %2};" : "=l"(d) : "f"(x), "f"(y));
    return d;
}
__device__ __forceinline__ ull cvt2(unsigned v) {      // half2 bits -> packed f32x2
    __half2 h = *reinterpret_cast<__half2*>(&v);
    float2 f = __half22float2(h);
    return pk2(f.x, f.y);
}
__device__ __forceinline__ float lo_(ull v) { return __uint_as_float((unsigned)v); }
__device__ __forceinline__ float hi_(ull v) { return __uint_as_float((unsigned)(v >> 32)); }

__device__ __forceinline__ float tanhfast(float x) {
    float y;
    asm("tanh.approx.f32 %0, %1;" : "=f"(y) : "f"(x));
    return y;
}
// gate pre-scaled by 0.5: sigma(2y) = 0.5*tanh(y)+0.5
__device__ __forceinline__ float sigp(float y) { return fmaf(0.5f, tanhfast(y), 0.5f); }

// ---------------------------------------------------------------------------
// 1 warp per CTA, 4 batch rows, warp-autonomous recurrence.
// Lane L owns units {L, L+32}; f32x2 packs (i,f) and (g,o).
// k<KC: fp32 weights in registers. k>=KC: fp16 table, ONE LDG.128 per k
// (halves the weight wavefronts), converted to f32x2 on the ALU pipe.
// ---------------------------------------------------------------------------
__global__ __launch_bounds__(32) void lstm_kernel(const int* __restrict__ tokens,
                                                  float* __restrict__ out)
{
    __shared__ __align__(16) float2 sH[ROWS][SROW];

    const int lane = threadIdx.x;
    const int b0   = blockIdx.x * ROWS;
    const int u1   = lane;
    const int u2   = lane + 32;
    const bool live2 = (u2 < HID);

    for (int i = lane; i < ROWS * SROW; i += 32)
        (&sH[0][0])[i] = make_float2(0.f, 0.f);
    __syncwarp();

    float c1[ROWS], c2[ROWS];
    #pragma unroll
    for (int j = 0; j < ROWS; j++) { c1[j] = 0.f; c2[j] = 0.f; }

    // register-cached fp32 weights for k = 0..KC-1
    ull cw[KC * 4];
    #pragma unroll
    for (int k = 0; k < KC; k++) {
        ulonglong2 a = __ldg(reinterpret_cast<const ulonglong2*>(gWk + k * HP + u1));
        ulonglong2 b = __ldg(reinterpret_cast<const ulonglong2*>(gWk + k * HP + u2));
        cw[k * 4 + 0] = a.x;  cw[k * 4 + 1] = a.y;
        cw[k * 4 + 2] = b.x;  cw[k * 4 + 3] = b.y;
    }

    const float4* __restrict__ Xp = gXT;
    const uint4*  __restrict__ Hp = reinterpret_cast<const uint4*>(gWH);

    const int* tp[ROWS];
    int tk[ROWS];
    #pragma unroll
    for (int j = 0; j < ROWS; j++) {
        tp[j] = tokens + (size_t)(b0 + j) * TLEN;
        tk[j] = __ldg(tp[j]);
    }

    for (int t = 0; t < TLEN; ++t) {
        const int t2 = (t + 1 < TLEN) ? t + 1 : t;
        int tkn[ROWS];
        #pragma unroll
        for (int j = 0; j < ROWS; j++) tkn[j] = __ldg(tp[j] + t2);

        // accumulators init from token gate-init table
        ull a1if[ROWS], a1go[ROWS], a2if[ROWS], a2go[ROWS];
        #pragma unroll
        for (int j = 0; j < ROWS; j++) {
            ulonglong2 v0 = __ldg(reinterpret_cast<const ulonglong2*>(Xp + tk[j] * HP + u1));
            ulonglong2 v1 = __ldg(reinterpret_cast<const ulonglong2*>(Xp + tk[j] * HP + u2));
            a1if[j] = v0.x;  a1go[j] = v0.y;
            a2if[j] = v1.x;  a2go[j] = v1.y;
        }

        // ---- cached k's: zero weight traffic
        #pragma unroll
        for (int k = 0; k < KC; k += 2) {
            const ull wA0if = cw[k * 4 + 0], wA0go = cw[k * 4 + 1];
            const ull wA1if = cw[k * 4 + 2], wA1go = cw[k * 4 + 3];
            const ull wB0if = cw[k * 4 + 4], wB0go = cw[k * 4 + 5];
            const ull wB1if = cw[k * 4 + 6], wB1go = cw[k * 4 + 7];
            #pragma unroll
            for (int j = 0; j < ROWS; j++) {
                ulonglong2 hh = *reinterpret_cast<const ulonglong2*>(&sH[j][k]);
                a1if[j] = ffma2(wA0if, hh.x, a1if[j]);
                a1go[j] = ffma2(wA0go, hh.x, a1go[j]);
                a2if[j] = ffma2(wA1if, hh.x, a2if[j]);
                a2go[j] = ffma2(wA1go, hh.x, a2go[j]);
                a1if[j] = ffma2(wB0if, hh.y, a1if[j]);
                a1go[j] = ffma2(wB0go, hh.y, a1go[j]);
                a2if[j] = ffma2(wB1if, hh.y, a2if[j]);
                a2go[j] = ffma2(wB1go, hh.y, a2go[j]);
            }
        }

        // ---- streamed k's: fp16 table, one LDG.128 per k, cvt on ALU pipe
        #pragma unroll
        for (int k = KC; k < HID; k += 2) {
            uint4 wa = __ldg(Hp + (k - KC) * 32 + lane);
            uint4 wb = __ldg(Hp + (k + 1 - KC) * 32 + lane);
            ull wA0if = cvt2(wa.x), wA0go = cvt2(wa.y);
            ull wA1if = cvt2(wa.z), wA1go = cvt2(wa.w);
            ull wB0if = cvt2(wb.x), wB0go = cvt2(wb.y);
            ull wB1if = cvt2(wb.z), wB1go = cvt2(wb.w);
            #pragma unroll
            for (int j = 0; j < ROWS; j++) {
                ulonglong2 hh = *reinterpret_cast<const ulonglong2*>(&sH[j][k]);
                a1if[j] = ffma2(wA0if, hh.x, a1if[j]);
                a1go[j] = ffma2(wA0go, hh.x, a1go[j]);
                a2if[j] = ffma2(wA1if, hh.x, a2if[j]);
                a2go[j] = ffma2(wA1go, hh.x, a2go[j]);
                a1if[j] = ffma2(wB0if, hh.y, a1if[j]);
                a1go[j] = ffma2(wB0go, hh.y, a1go[j]);
                a2if[j] = ffma2(wB1if, hh.y, a2if[j]);
                a2go[j] = ffma2(wB1go, hh.y, a2go[j]);
            }
        }

        __syncwarp();

        #pragma unroll
        for (int j = 0; j < ROWS; j++) {
            const bool live = (tk[j] != 0);
            {   // unit u1
                float i = sigp(lo_(a1if[j]));
                float f = sigp(hi_(a1if[j]));
                float g = tanhfast(lo_(a1go[j]));
                float o = sigp(hi_(a1go[j]));
                float cn = fmaf(f, c1[j], i * g);
                float hn = o * tanhfast(cn);
                if (live) { c1[j] = cn; sH[j][u1] = make_float2(hn, hn); }
            }
            if (live2) {   // unit u2
                float i = sigp(lo_(a2if[j]));
                float f = sigp(hi_(a2if[j]));
                float g = tanhfast(lo_(a2go[j]));
                float o = sigp(hi_(a2go[j]));
                float cn = fmaf(f, c2[j], i * g);
                float hn = o * tanhfast(cn);
                if (live) { c2[j] = cn; sH[j][u2] = make_float2(hn, hn); }
            }
        }
        __syncwarp();

        #pragma unroll
        for (int j = 0; j < ROWS; j++) tk[j] = tkn[j];
    }

    // collapsed MLP head: out = sigmoid(c0 + q . h_final)   (accurate sigmoid)
    if (lane < ROWS) {
        const int j = lane;
        float s = gc0;
        #pragma unroll 10
        for (int k = 0; k < HID; k++) s += gq[k] * sH[j][k].x;
        out[b0 + j] = 1.0f / (1.0f + __expf(-s));
    }
}

// ---------------------------------------------------------------------------
extern "C" void kernel_launch(void* const* d_in, const int* in_sizes, int n_in,
                              void* d_out, int out_size)
{
    const int*   tokens = (const int*)  d_in[0];
    const float* emb    = (const float*)d_in[1];
    const float* W_ih   = (const float*)d_in[2];
    const float* W_hh   = (const float*)d_in[3];
    const float* b_ih   = (const float*)d_in[4];
    const float* b_hh   = (const float*)d_in[5];
    const float* W1     = (const float*)d_in[6];
    const float* b1     = (const float*)d_in[7];
    const float* W2     = (const float*)d_in[8];
    const float* b2     = (const float*)d_in[9];
    float* out = (float*)d_out;

    prep_kernel<<<1, 256>>>(emb, W_ih, W_hh, b_ih, b_hh, W1, b1, W2, b2);
    lstm_kernel<<<NBATCH / ROWS, 32>>>(tokens, out);
}

// round 8
// speedup vs baseline: 1.2884x; 1.2884x over previous
#include <cuda_runtime.h>
#include <cstdint>

#define VOCAB 14
#define EMBED 10
#define HID   50
#define HP    64          // padded unit slots (cached-k + gate-init tables)
#define KC    12          // k's cached in registers (96 regs)
#define SROWF 56          // sH row stride in floats (224B, 16B-aligned groups)
#define TLEN  2048
#define NBATCH 4096
#define ROWS  4           // batch rows per warp

typedef unsigned long long ull;

// gWk[k][u] (fp32, padded u<64): (0.5*Wi, 0.5*Wf, Wg, 0.5*Wo) — k<KC reg-cached
// gWs[(k-KC)*50 + u] (compact): same — streamed k>=KC (+32 pad for dead-lane overread)
// gXT[v][u] (fp32): per-token gate init, same scaling
__device__ float4 gWk[HID * HP];
__device__ float4 gWs[(HID - KC) * HID + 32];
__device__ float4 gXT[VOCAB * HP];
__device__ float  gq[HID];
__device__ float  gc0;

// ---------------------------------------------------------------------------
__global__ void prep_kernel(const float* __restrict__ emb,
                            const float* __restrict__ W_ih,
                            const float* __restrict__ W_hh,
                            const float* __restrict__ b_ih,
                            const float* __restrict__ b_hh,
                            const float* __restrict__ W1,
                            const float* __restrict__ b1,
                            const float* __restrict__ W2,
                            const float* __restrict__ b2)
{
    int tid = threadIdx.x;

    for (int i = tid; i < HID * HP; i += blockDim.x) {
        int k = i / HP, u = i % HP;
        float4 w = make_float4(0.f, 0.f, 0.f, 0.f);
        if (u < HID) {
            w.x = 0.5f * W_hh[(0 * HID + u) * HID + k];
            w.y = 0.5f * W_hh[(1 * HID + u) * HID + k];
            w.z =        W_hh[(2 * HID + u) * HID + k];
            w.w = 0.5f * W_hh[(3 * HID + u) * HID + k];
        }
        gWk[i] = w;
    }

    for (int i = tid; i < (HID - KC) * HID + 32; i += blockDim.x) {
        float4 w = make_float4(0.f, 0.f, 0.f, 0.f);
        if (i < (HID - KC) * HID) {
            int k = KC + i / HID, u = i % HID;
            w.x = 0.5f * W_hh[(0 * HID + u) * HID + k];
            w.y = 0.5f * W_hh[(1 * HID + u) * HID + k];
            w.z =        W_hh[(2 * HID + u) * HID + k];
            w.w = 0.5f * W_hh[(3 * HID + u) * HID + k];
        }
        gWs[i] = w;
    }

    for (int i = tid; i < VOCAB * HP; i += blockDim.x) {
        int v = i / HP, u = i % HP;
        float4 x = make_float4(0.f, 0.f, 0.f, 0.f);
        if (u < HID) {
            float* px = reinterpret_cast<float*>(&x);
            #pragma unroll
            for (int g = 0; g < 4; g++) {
                int c = g * HID + u;
                float s = b_ih[c] + b_hh[c];
                #pragma unroll
                for (int e = 0; e < EMBED; e++)
                    s += emb[v * EMBED + e] * W_ih[c * EMBED + e];
                px[g] = (g == 2) ? s : 0.5f * s;
            }
        }
        gXT[i] = x;
    }

    for (int u = tid; u < HID; u += blockDim.x) {
        float s = 0.f;
        for (int m = 0; m < HID; m++) s += W2[m] * W1[m * HID + u];
        gq[u] = s;
    }
    if (tid == 0) {
        float s = b2[0];
        for (int m = 0; m < HID; m++) s += W2[m] * b1[m];
        gc0 = s;
    }
}

// ---------------------------------------------------------------------------
__device__ __forceinline__ ull ffma2(ull a, ull b, ull c) {
    ull d;
    asm("fma.rn.f32x2 %0, %1, %2, %3;" : "=l"(d) : "l"(a), "l"(b), "l"(c));
    return d;
}
__device__ __forceinline__ ull dup_(float x) {         // (x,x) packed f32x2
    ull d;
    asm("mov.b64 %0, {%1, %1};" : "=l"(d) : "f"(x));
    return d;
}
__device__ __forceinline__ float lo_(ull v) { return __uint_as_float((unsigned)v); }
__device__ __forceinline__ float hi_(ull v) { return __uint_as_float((unsigned)(v >> 32)); }

__device__ __forceinline__ float tanhfast(float x) {
    float y;
    asm("tanh.approx.f32 %0, %1;" : "=f"(y) : "f"(x));
    return y;
}
// gate pre-scaled by 0.5: sigma(2y) = 0.5*tanh(y)+0.5
__device__ __forceinline__ float sigp(float y) { return fmaf(0.5f, tanhfast(y), 0.5f); }

// one k-pair of FFMA2 for all rows, given weight pairs and h-dups
#define KPAIR(W0if, W0go, W1if, W1go, V0if, V0go, V1if, V1go, HA, HB)          \
    _Pragma("unroll")                                                          \
    for (int j = 0; j < ROWS; j++) {                                           \
        a1if[j] = ffma2(W0if, HA[j], a1if[j]);                                 \
        a1go[j] = ffma2(W0go, HA[j], a1go[j]);                                 \
        a2if[j] = ffma2(W1if, HA[j], a2if[j]);                                 \
        a2go[j] = ffma2(W1go, HA[j], a2go[j]);                                 \
        a1if[j] = ffma2(V0if, HB[j], a1if[j]);                                 \
        a1go[j] = ffma2(V0go, HB[j], a1go[j]);                                 \
        a2if[j] = ffma2(V1if, HB[j], a2if[j]);                                 \
        a2go[j] = ffma2(V1go, HB[j], a2go[j]);                                 \
    }

// ---------------------------------------------------------------------------
// 1 warp per CTA, 4 batch rows, warp-autonomous recurrence.
// Lane L owns units {L, L+32}; f32x2 packs (i,f) and (g,o).
// h stored plain: one LDS.128 covers 4 k's per row; (h,h) rebuilt by MOV dups
// on the idle ALU pipe. k<KC weights in registers; k>=KC streamed fp32.
// ---------------------------------------------------------------------------
__global__ __launch_bounds__(32) void lstm_kernel(const int* __restrict__ tokens,
                                                  float* __restrict__ out)
{
    __shared__ __align__(16) float sH[ROWS][SROWF];

    const int lane = threadIdx.x;
    const int b0   = blockIdx.x * ROWS;
    const int u1   = lane;
    const int u2   = lane + 32;
    const bool live2 = (u2 < HID);

    for (int i = lane; i < ROWS * SROWF; i += 32)
        (&sH[0][0])[i] = 0.f;
    __syncwarp();

    float c1[ROWS], c2[ROWS];
    #pragma unroll
    for (int j = 0; j < ROWS; j++) { c1[j] = 0.f; c2[j] = 0.f; }

    // register-cached fp32 weights for k = 0..KC-1
    ull cw[KC * 4];
    #pragma unroll
    for (int k = 0; k < KC; k++) {
        ulonglong2 a = __ldg(reinterpret_cast<const ulonglong2*>(gWk + k * HP + u1));
        ulonglong2 b = __ldg(reinterpret_cast<const ulonglong2*>(gWk + k * HP + u2));
        cw[k * 4 + 0] = a.x;  cw[k * 4 + 1] = a.y;
        cw[k * 4 + 2] = b.x;  cw[k * 4 + 3] = b.y;
    }

    const float4* __restrict__ Xp = gXT;
    const float4* __restrict__ Sp = gWs;

    const int* tp[ROWS];
    int tk[ROWS];
    #pragma unroll
    for (int j = 0; j < ROWS; j++) {
        tp[j] = tokens + (size_t)(b0 + j) * TLEN;
        tk[j] = __ldg(tp[j]);
    }

    for (int t = 0; t < TLEN; ++t) {
        const int t2 = (t + 1 < TLEN) ? t + 1 : t;
        int tkn[ROWS];
        #pragma unroll
        for (int j = 0; j < ROWS; j++) tkn[j] = __ldg(tp[j] + t2);

        // accumulators init from token gate-init table
        ull a1if[ROWS], a1go[ROWS], a2if[ROWS], a2go[ROWS];
        #pragma unroll
        for (int j = 0; j < ROWS; j++) {
            ulonglong2 v0 = __ldg(reinterpret_cast<const ulonglong2*>(Xp + tk[j] * HP + u1));
            ulonglong2 v1 = __ldg(reinterpret_cast<const ulonglong2*>(Xp + tk[j] * HP + u2));
            a1if[j] = v0.x;  a1go[j] = v0.y;
            a2if[j] = v1.x;  a2go[j] = v1.y;
        }

        // ---- cached k's (0..KC-1), groups of 4: 1 LDS.128 per row per group
        #pragma unroll
        for (int kg = 0; kg < KC; kg += 4) {
            float4 hv[ROWS];
            ull hA[ROWS], hB[ROWS], hC[ROWS], hD[ROWS];
            #pragma unroll
            for (int j = 0; j < ROWS; j++) {
                hv[j] = *reinterpret_cast<const float4*>(&sH[j][kg]);
                hA[j] = dup_(hv[j].x);  hB[j] = dup_(hv[j].y);
                hC[j] = dup_(hv[j].z);  hD[j] = dup_(hv[j].w);
            }
            KPAIR(cw[kg*4+0], cw[kg*4+1], cw[kg*4+2], cw[kg*4+3],
                  cw[kg*4+4], cw[kg*4+5], cw[kg*4+6], cw[kg*4+7], hA, hB)
            KPAIR(cw[kg*4+8], cw[kg*4+9], cw[kg*4+10], cw[kg*4+11],
                  cw[kg*4+12], cw[kg*4+13], cw[kg*4+14], cw[kg*4+15], hC, hD)
        }

        // ---- streamed k's (KC..47), groups of 4
        #pragma unroll
        for (int kg = KC; kg < 48; kg += 4) {
            const float4* p0 = Sp + (kg + 0 - KC) * HID;
            const float4* p1 = Sp + (kg + 1 - KC) * HID;
            const float4* p2 = Sp + (kg + 2 - KC) * HID;
            const float4* p3 = Sp + (kg + 3 - KC) * HID;
            ulonglong2 w0a = __ldg(reinterpret_cast<const ulonglong2*>(p0 + u1));
            ulonglong2 w0b = __ldg(reinterpret_cast<const ulonglong2*>(p0 + u2));
            ulonglong2 w1a = __ldg(reinterpret_cast<const ulonglong2*>(p1 + u1));
            ulonglong2 w1b = __ldg(reinterpret_cast<const ulonglong2*>(p1 + u2));
            ulonglong2 w2a = __ldg(reinterpret_cast<const ulonglong2*>(p2 + u1));
            ulonglong2 w2b = __ldg(reinterpret_cast<const ulonglong2*>(p2 + u2));
            ulonglong2 w3a = __ldg(reinterpret_cast<const ulonglong2*>(p3 + u1));
            ulonglong2 w3b = __ldg(reinterpret_cast<const ulonglong2*>(p3 + u2));
            float4 hv[ROWS];
            ull hA[ROWS], hB[ROWS], hC[ROWS], hD[ROWS];
            #pragma unroll
            for (int j = 0; j < ROWS; j++) {
                hv[j] = *reinterpret_cast<const float4*>(&sH[j][kg]);
                hA[j] = dup_(hv[j].x);  hB[j] = dup_(hv[j].y);
                hC[j] = dup_(hv[j].z);  hD[j] = dup_(hv[j].w);
            }
            KPAIR(w0a.x, w0a.y, w0b.x, w0b.y, w1a.x, w1a.y, w1b.x, w1b.y, hA, hB)
            KPAIR(w2a.x, w2a.y, w2b.x, w2b.y, w3a.x, w3a.y, w3b.x, w3b.y, hC, hD)
        }

        // ---- final pair k = 48, 49
        {
            const float4* p0 = Sp + (48 - KC) * HID;
            const float4* p1 = Sp + (49 - KC) * HID;
            ulonglong2 w0a = __ldg(reinterpret_cast<const ulonglong2*>(p0 + u1));
            ulonglong2 w0b = __ldg(reinterpret_cast<const ulonglong2*>(p0 + u2));
            ulonglong2 w1a = __ldg(reinterpret_cast<const ulonglong2*>(p1 + u1));
            ulonglong2 w1b = __ldg(reinterpret_cast<const ulonglong2*>(p1 + u2));
            ull hA[ROWS], hB[ROWS];
            #pragma unroll
            for (int j = 0; j < ROWS; j++) {
                float2 hv = *reinterpret_cast<const float2*>(&sH[j][48]);
                hA[j] = dup_(hv.x);  hB[j] = dup_(hv.y);
            }
            KPAIR(w0a.x, w0a.y, w0b.x, w0b.y, w1a.x, w1a.y, w1b.x, w1b.y, hA, hB)
        }

        __syncwarp();

        #pragma unroll
        for (int j = 0; j < ROWS; j++) {
            const bool live = (tk[j] != 0);
            {   // unit u1
                float i = sigp(lo_(a1if[j]));
                float f = sigp(hi_(a1if[j]));
                float g = tanhfast(lo_(a1go[j]));
                float o = sigp(hi_(a1go[j]));
                float cn = fmaf(f, c1[j], i * g);
                float hn = o * tanhfast(cn);
                if (live) { c1[j] = cn; sH[j][u1] = hn; }
            }
            if (live2) {   // unit u2
                float i = sigp(lo_(a2if[j]));
                float f = sigp(hi_(a2if[j]));
                float g = tanhfast(lo_(a2go[j]));
                float o = sigp(hi_(a2go[j]));
                float cn = fmaf(f, c2[j], i * g);
                float hn = o * tanhfast(cn);
                if (live) { c2[j] = cn; sH[j][u2] = hn; }
            }
        }
        __syncwarp();

        #pragma unroll
        for (int j = 0; j < ROWS; j++) tk[j] = tkn[j];
    }

    // collapsed MLP head: out = sigmoid(c0 + q . h_final)   (accurate sigmoid)
    if (lane < ROWS) {
        const int j = lane;
        float s = gc0;
        #pragma unroll 10
        for (int k = 0; k < HID; k++) s += gq[k] * sH[j][k];
        out[b0 + j] = 1.0f / (1.0f + __expf(-s));
    }
}

// ---------------------------------------------------------------------------
extern "C" void kernel_launch(void* const* d_in, const int* in_sizes, int n_in,
                              void* d_out, int out_size)
{
    const int*   tokens = (const int*)  d_in[0];
    const float* emb    = (const float*)d_in[1];
    const float* W_ih   = (const float*)d_in[2];
    const float* W_hh   = (const float*)d_in[3];
    const float* b_ih   = (const float*)d_in[4];
    const float* b_hh   = (const float*)d_in[5];
    const float* W1     = (const float*)d_in[6];
    const float* b1     = (const float*)d_in[7];
    const float* W2     = (const float*)d_in[8];
    const float* b2     = (const float*)d_in[9];
    float* out = (float*)d_out;

    prep_kernel<<<1, 256>>>(emb, W_ih, W_hh, b_ih, b_hh, W1, b1, W2, b2);
    lstm_kernel<<<NBATCH / ROWS, 32>>>(tokens, out);
}